// round 1
// baseline (speedup 1.0000x reference)
#include <cuda_runtime.h>
#include <cstdint>

#define NN 100000
#define EE 1600000
#define NC 10000
#define GG 1000
#define ND 32
#define ED 8
#define NL 4

// ---------------- scratch (device globals; no allocation allowed) -----------
__device__ float g_h[NN * ND];      // node embeddings (12.8 MB)
__device__ float g_e[EE * ED];      // edge embeddings (51.2 MB)
__device__ float g_P[NN * ED];      // h @ We[l][0:32]   (src half)
__device__ float g_Q[NN * ED];      // h @ We[l][32:64]  (dst half)
__device__ float g_agg[NN * ED];    // segment-sum accumulator (zero-invariant across calls)
__device__ float g_logits[NC];
__device__ unsigned g_mx[GG];       // encoded float max
__device__ float g_sum[GG];

// ---------------- helpers ----------------------------------------------------
__device__ __forceinline__ unsigned enc_f(float f) {
    unsigned u = __float_as_uint(f);
    return (u & 0x80000000u) ? ~u : (u | 0x80000000u);
}
__device__ __forceinline__ float dec_f(unsigned u) {
    return (u & 0x80000000u) ? __uint_as_float(u & 0x7FFFFFFFu)
                             : __uint_as_float(~u);
}
__device__ __forceinline__ void red_add_v4(float* p, float a, float b, float c, float d) {
    asm volatile("red.global.add.v4.f32 [%0], {%1,%2,%3,%4};"
                 :: "l"(p), "f"(a), "f"(b), "f"(c), "f"(d) : "memory");
}

// ---------------- init: e = edge_attr @ We_in + be_in ------------------------
__global__ void k_init_edges(const float* __restrict__ edge_attr,
                             const float* __restrict__ We_in,
                             const float* __restrict__ be_in) {
    __shared__ float sw[ED], sb[ED];
    if (threadIdx.x < ED) { sw[threadIdx.x] = We_in[threadIdx.x]; sb[threadIdx.x] = be_in[threadIdx.x]; }
    __syncthreads();
    int i = blockIdx.x * blockDim.x + threadIdx.x;
    if (i >= EE) return;
    float a = edge_attr[i];
    float v[ED];
#pragma unroll
    for (int j = 0; j < ED; j++) v[j] = a * sw[j] + sb[j];
    float4* out = (float4*)(g_e + (size_t)i * ED);
    out[0] = make_float4(v[0], v[1], v[2], v[3]);
    out[1] = make_float4(v[4], v[5], v[6], v[7]);
}

// ---------------- init: h = x @ Wn_in + bn_in; P0/Q0 from We_l[0] ------------
__global__ void k_init_nodes(const float* __restrict__ x,
                             const float* __restrict__ Wn_in,
                             const float* __restrict__ bn_in,
                             const float* __restrict__ We_l) {  // layer 0 block
    __shared__ float sW[2 * ND], sB[ND], sWa[ND * ED], sWb[ND * ED];
    for (int t = threadIdx.x; t < 2 * ND; t += blockDim.x) sW[t] = Wn_in[t];
    for (int t = threadIdx.x; t < ND; t += blockDim.x) sB[t] = bn_in[t];
    for (int t = threadIdx.x; t < ND * ED; t += blockDim.x) {
        sWa[t] = We_l[t];               // rows 0..31
        sWb[t] = We_l[ND * ED + t];     // rows 32..63
    }
    __syncthreads();
    int i = blockIdx.x * blockDim.x + threadIdx.x;
    if (i >= NN) return;
    float x0 = x[2 * i], x1 = x[2 * i + 1];
    float h[ND];
#pragma unroll
    for (int j = 0; j < ND; j++) h[j] = x0 * sW[j] + x1 * sW[ND + j] + sB[j];
    float4* ho = (float4*)(g_h + (size_t)i * ND);
#pragma unroll
    for (int j4 = 0; j4 < ND / 4; j4++)
        ho[j4] = make_float4(h[4*j4], h[4*j4+1], h[4*j4+2], h[4*j4+3]);
    float p[ED], q[ED];
#pragma unroll
    for (int t = 0; t < ED; t++) { p[t] = 0.f; q[t] = 0.f; }
#pragma unroll
    for (int k = 0; k < ND; k++) {
        float hk = h[k];
#pragma unroll
        for (int t = 0; t < ED; t++) {
            p[t] += hk * sWa[k * ED + t];
            q[t] += hk * sWb[k * ED + t];
        }
    }
    float4* po = (float4*)(g_P + (size_t)i * ED);
    po[0] = make_float4(p[0], p[1], p[2], p[3]);
    po[1] = make_float4(p[4], p[5], p[6], p[7]);
    float4* qo = (float4*)(g_Q + (size_t)i * ED);
    qo[0] = make_float4(q[0], q[1], q[2], q[3]);
    qo[1] = make_float4(q[4], q[5], q[6], q[7]);
}

// ---------------- per-layer edge kernel --------------------------------------
// new_e = relu(P[src] + Q[dst] + e @ Wc + be);  agg[dst] += new_e;  e += new_e
__global__ void k_edge(const int* __restrict__ edge_index,
                       const float* __restrict__ We_l,   // full [L,72,8]
                       const float* __restrict__ be_l,   // full [L,8]
                       int layer) {
    __shared__ float sWc[ED * ED], sBe[ED];
    {
        const float* Wc = We_l + (size_t)layer * (2 * ND + ED) * ED + 2 * ND * ED;
        if (threadIdx.x < ED * ED) sWc[threadIdx.x] = Wc[threadIdx.x];
        if (threadIdx.x < ED) sBe[threadIdx.x] = be_l[layer * ED + threadIdx.x];
    }
    __syncthreads();
    int i = blockIdx.x * blockDim.x + threadIdx.x;
    if (i >= EE) return;
    int src = edge_index[i];
    int dst = edge_index[EE + i];
    // issue random gathers early
    const float4* pp = (const float4*)(g_P + (size_t)src * ED);
    const float4* qq = (const float4*)(g_Q + (size_t)dst * ED);
    float4 p0 = pp[0], p1 = pp[1];
    float4 q0 = qq[0], q1 = qq[1];
    float4* ep = (float4*)(g_e + (size_t)i * ED);
    float4 e0 = ep[0], e1 = ep[1];
    float m[ED] = {e0.x, e0.y, e0.z, e0.w, e1.x, e1.y, e1.z, e1.w};
    float t[ED];
#pragma unroll
    for (int j = 0; j < ED; j++) t[j] = sBe[j];
#pragma unroll
    for (int k = 0; k < ED; k++) {
        float mk = m[k];
#pragma unroll
        for (int j = 0; j < ED; j++) t[j] += mk * sWc[k * ED + j];
    }
    float pa[ED] = {p0.x, p0.y, p0.z, p0.w, p1.x, p1.y, p1.z, p1.w};
    float qa[ED] = {q0.x, q0.y, q0.z, q0.w, q1.x, q1.y, q1.z, q1.w};
    float ne[ED];
#pragma unroll
    for (int j = 0; j < ED; j++) {
        float v = t[j] + pa[j] + qa[j];
        ne[j] = v > 0.f ? v : 0.f;
    }
    float* ap = g_agg + (size_t)dst * ED;
    red_add_v4(ap,     ne[0], ne[1], ne[2], ne[3]);
    red_add_v4(ap + 4, ne[4], ne[5], ne[6], ne[7]);
    ep[0] = make_float4(m[0] + ne[0], m[1] + ne[1], m[2] + ne[2], m[3] + ne[3]);
    ep[1] = make_float4(m[4] + ne[4], m[5] + ne[5], m[6] + ne[6], m[7] + ne[7]);
}

// ---------------- per-layer node kernel --------------------------------------
// h += relu([h, agg] @ Wn + bn); re-zero agg; if not last, compute next P/Q.
__global__ void k_node(const float* __restrict__ Wn_l,  // full [L,40,32]
                       const float* __restrict__ bn_l,  // full [L,32]
                       const float* __restrict__ We_l,  // full [L,72,8]
                       int layer, int last) {
    __shared__ float sWn[(ND + ED) * ND], sBn[ND];
    __shared__ float sWa[ND * ED], sWb[ND * ED];
    {
        const float* Wn = Wn_l + (size_t)layer * (ND + ED) * ND;
        for (int tt = threadIdx.x; tt < (ND + ED) * ND; tt += blockDim.x) sWn[tt] = Wn[tt];
        for (int tt = threadIdx.x; tt < ND; tt += blockDim.x) sBn[tt] = bn_l[layer * ND + tt];
        if (!last) {
            const float* Wa = We_l + (size_t)(layer + 1) * (2 * ND + ED) * ED;
            for (int tt = threadIdx.x; tt < ND * ED; tt += blockDim.x) {
                sWa[tt] = Wa[tt];
                sWb[tt] = Wa[ND * ED + tt];
            }
        }
    }
    __syncthreads();
    int i = blockIdx.x * blockDim.x + threadIdx.x;
    if (i >= NN) return;
    float m[ND + ED];
    float4* hp = (float4*)(g_h + (size_t)i * ND);
#pragma unroll
    for (int j4 = 0; j4 < ND / 4; j4++) {
        float4 v = hp[j4];
        m[4*j4] = v.x; m[4*j4+1] = v.y; m[4*j4+2] = v.z; m[4*j4+3] = v.w;
    }
    float4* ag = (float4*)(g_agg + (size_t)i * ED);
    float4 a0 = ag[0], a1 = ag[1];
    m[ND+0]=a0.x; m[ND+1]=a0.y; m[ND+2]=a0.z; m[ND+3]=a0.w;
    m[ND+4]=a1.x; m[ND+5]=a1.y; m[ND+6]=a1.z; m[ND+7]=a1.w;
    // reset agg for next layer / next replay (zero-invariant)
    ag[0] = make_float4(0.f, 0.f, 0.f, 0.f);
    ag[1] = make_float4(0.f, 0.f, 0.f, 0.f);

    float acc[ND];
#pragma unroll
    for (int j = 0; j < ND; j++) acc[j] = sBn[j];
    for (int k = 0; k < ND + ED; k++) {
        float mk = m[k];
#pragma unroll
        for (int j = 0; j < ND; j++) acc[j] += mk * sWn[k * ND + j];
    }
    float hn[ND];
#pragma unroll
    for (int j = 0; j < ND; j++) {
        float r = acc[j] > 0.f ? acc[j] : 0.f;
        hn[j] = m[j] + r;
    }
#pragma unroll
    for (int j4 = 0; j4 < ND / 4; j4++)
        hp[j4] = make_float4(hn[4*j4], hn[4*j4+1], hn[4*j4+2], hn[4*j4+3]);

    if (!last) {
        float p[ED], q[ED];
#pragma unroll
        for (int t = 0; t < ED; t++) { p[t] = 0.f; q[t] = 0.f; }
#pragma unroll
        for (int k = 0; k < ND; k++) {
            float hk = hn[k];
#pragma unroll
            for (int t = 0; t < ED; t++) {
                p[t] += hk * sWa[k * ED + t];
                q[t] += hk * sWb[k * ED + t];
            }
        }
        float4* po = (float4*)(g_P + (size_t)i * ED);
        po[0] = make_float4(p[0], p[1], p[2], p[3]);
        po[1] = make_float4(p[4], p[5], p[6], p[7]);
        float4* qo = (float4*)(g_Q + (size_t)i * ED);
        qo[0] = make_float4(q[0], q[1], q[2], q[3]);
        qo[1] = make_float4(q[4], q[5], q[6], q[7]);
    }
}

// ---------------- final stage -------------------------------------------------
__global__ void k_zero_pg() {
    int i = blockIdx.x * blockDim.x + threadIdx.x;
    if (i < GG) { g_mx[i] = 0u; g_sum[i] = 0.f; }
}

__global__ void k_cand(const int* __restrict__ cand,
                       const int* __restrict__ batch,
                       const float* __restrict__ Wout,
                       const float* __restrict__ bout) {
    int c = blockIdx.x * blockDim.x + threadIdx.x;
    if (c >= NC) return;
    int node = cand[c];
    const float* hr = g_h + (size_t)node * ND;
    float v = bout[0];
#pragma unroll
    for (int j = 0; j < ND; j++) v += hr[j] * Wout[j];
    g_logits[c] = v;
    int gidx = batch[node];
    atomicMax(&g_mx[gidx], enc_f(v));
}

__global__ void k_shift(const int* __restrict__ cand,
                        const int* __restrict__ batch,
                        float* __restrict__ out) {
    int c = blockIdx.x * blockDim.x + threadIdx.x;
    if (c >= NC) return;
    int gidx = batch[cand[c]];
    float s = g_logits[c] - dec_f(g_mx[gidx]);
    out[c] = s;
    atomicAdd(&g_sum[gidx], expf(s));
}

__global__ void k_finish(const int* __restrict__ cand,
                         const int* __restrict__ batch,
                         float* __restrict__ out) {
    int c = blockIdx.x * blockDim.x + threadIdx.x;
    if (c >= NC) return;
    int gidx = batch[cand[c]];
    out[c] = out[c] - logf(g_sum[gidx]);
}

// ---------------- launch ------------------------------------------------------
extern "C" void kernel_launch(void* const* d_in, const int* in_sizes, int n_in,
                              void* d_out, int out_size) {
    const float* x        = (const float*)d_in[0];
    const float* edge_attr= (const float*)d_in[1];
    const float* Wn_in    = (const float*)d_in[2];
    const float* bn_in    = (const float*)d_in[3];
    const float* We_in    = (const float*)d_in[4];
    const float* be_in    = (const float*)d_in[5];
    const float* We_l     = (const float*)d_in[6];
    const float* be_l     = (const float*)d_in[7];
    const float* Wn_l     = (const float*)d_in[8];
    const float* bn_l     = (const float*)d_in[9];
    const float* Wout     = (const float*)d_in[10];
    const float* bout     = (const float*)d_in[11];
    const int*   edge_index = (const int*)d_in[12];
    const int*   batch    = (const int*)d_in[13];
    const int*   cand     = (const int*)d_in[14];
    float* out = (float*)d_out;

    const int TB = 256;
    const int gE = (EE + TB - 1) / TB;
    const int gN = (NN + TB - 1) / TB;
    const int gC = (NC + TB - 1) / TB;
    const int gG = (GG + TB - 1) / TB;

    k_zero_pg<<<gG, TB>>>();
    k_init_edges<<<gE, TB>>>(edge_attr, We_in, be_in);
    k_init_nodes<<<gN, TB>>>(x, Wn_in, bn_in, We_l);
    for (int l = 0; l < NL; l++) {
        k_edge<<<gE, TB>>>(edge_index, We_l, be_l, l);
        k_node<<<gN, TB>>>(Wn_l, bn_l, We_l, l, (l == NL - 1) ? 1 : 0);
    }
    k_cand<<<gC, TB>>>(cand, batch, Wout, bout);
    k_shift<<<gC, TB>>>(cand, batch, out);
    k_finish<<<gC, TB>>>(cand, batch, out);
}

// round 3
// speedup vs baseline: 1.0543x; 1.0543x over previous
#include <cuda_runtime.h>
#include <cuda_fp16.h>
#include <cstdint>
#include <cstring>

#define NN 100000
#define EE 1600000
#define NC 10000
#define GG 1000
#define ND 32
#define ED 8
#define NL 4

// ---------------- scratch (device globals; no allocation allowed) -----------
__device__ float g_h[NN * ND];      // node embeddings (12.8 MB)
__device__ float g_e[EE * ED];      // edge embeddings (51.2 MB, fp32)
__device__ uint4 g_Ph[NN];          // h @ We[l][0:32]  packed fp16 x8 (16B/node)
__device__ uint4 g_Qh[NN];          // h @ We[l][32:64] packed fp16 x8
__device__ float g_agg[NN * ED];    // segment-sum accumulator (zero-invariant)
__device__ float g_logits[NC];
__device__ unsigned g_mx[GG];       // encoded float max
__device__ float g_sum[GG];

// ---------------- helpers ----------------------------------------------------
__device__ __forceinline__ unsigned enc_f(float f) {
    unsigned u = __float_as_uint(f);
    return (u & 0x80000000u) ? ~u : (u | 0x80000000u);
}
__device__ __forceinline__ float dec_f(unsigned u) {
    return (u & 0x80000000u) ? __uint_as_float(u & 0x7FFFFFFFu)
                             : __uint_as_float(~u);
}
__device__ __forceinline__ void red_add_v4(float* p, float a, float b, float c, float d) {
    asm volatile("red.global.add.v4.f32 [%0], {%1,%2,%3,%4};"
                 :: "l"(p), "f"(a), "f"(b), "f"(c), "f"(d) : "memory");
}
__device__ __forceinline__ unsigned h2u(__half2 h) {
    unsigned u; memcpy(&u, &h, 4); return u;
}
__device__ __forceinline__ float2 u2f2(unsigned u) {
    __half2 h; memcpy(&h, &u, 4); return __half22float2(h);
}
__device__ __forceinline__ uint4 pack8h(const float* v) {
    uint4 r;
    r.x = h2u(__floats2half2_rn(v[0], v[1]));
    r.y = h2u(__floats2half2_rn(v[2], v[3]));
    r.z = h2u(__floats2half2_rn(v[4], v[5]));
    r.w = h2u(__floats2half2_rn(v[6], v[7]));
    return r;
}
__device__ __forceinline__ void unpack8h(uint4 u, float* v) {
    float2 a = u2f2(u.x), b = u2f2(u.y), c = u2f2(u.z), d = u2f2(u.w);
    v[0]=a.x; v[1]=a.y; v[2]=b.x; v[3]=b.y; v[4]=c.x; v[5]=c.y; v[6]=d.x; v[7]=d.y;
}

// ---------------- init: e = edge_attr @ We_in + be_in ------------------------
__global__ void k_init_edges(const float* __restrict__ edge_attr,
                             const float* __restrict__ We_in,
                             const float* __restrict__ be_in) {
    __shared__ float sw[ED], sb[ED];
    if (threadIdx.x < ED) { sw[threadIdx.x] = We_in[threadIdx.x]; sb[threadIdx.x] = be_in[threadIdx.x]; }
    __syncthreads();
    int i = blockIdx.x * blockDim.x + threadIdx.x;
    if (i >= EE) return;
    float a = edge_attr[i];
    float v[ED];
#pragma unroll
    for (int j = 0; j < ED; j++) v[j] = a * sw[j] + sb[j];
    float4* out = (float4*)(g_e + (size_t)i * ED);
    out[0] = make_float4(v[0], v[1], v[2], v[3]);
    out[1] = make_float4(v[4], v[5], v[6], v[7]);
}

// ---------------- init: h = x @ Wn_in + bn_in; P0/Q0 from We_l[0] ------------
__global__ void k_init_nodes(const float* __restrict__ x,
                             const float* __restrict__ Wn_in,
                             const float* __restrict__ bn_in,
                             const float* __restrict__ We_l) {  // layer 0 block
    __shared__ float sW[2 * ND], sB[ND], sWa[ND * ED], sWb[ND * ED];
    for (int t = threadIdx.x; t < 2 * ND; t += blockDim.x) sW[t] = Wn_in[t];
    for (int t = threadIdx.x; t < ND; t += blockDim.x) sB[t] = bn_in[t];
    for (int t = threadIdx.x; t < ND * ED; t += blockDim.x) {
        sWa[t] = We_l[t];               // rows 0..31
        sWb[t] = We_l[ND * ED + t];     // rows 32..63
    }
    __syncthreads();
    int i = blockIdx.x * blockDim.x + threadIdx.x;
    if (i >= NN) return;
    float x0 = x[2 * i], x1 = x[2 * i + 1];
    float h[ND];
#pragma unroll
    for (int j = 0; j < ND; j++) h[j] = x0 * sW[j] + x1 * sW[ND + j] + sB[j];
    float4* ho = (float4*)(g_h + (size_t)i * ND);
#pragma unroll
    for (int j4 = 0; j4 < ND / 4; j4++)
        ho[j4] = make_float4(h[4*j4], h[4*j4+1], h[4*j4+2], h[4*j4+3]);
    float p[ED], q[ED];
#pragma unroll
    for (int t = 0; t < ED; t++) { p[t] = 0.f; q[t] = 0.f; }
#pragma unroll
    for (int k = 0; k < ND; k++) {
        float hk = h[k];
#pragma unroll
        for (int t = 0; t < ED; t++) {
            p[t] += hk * sWa[k * ED + t];
            q[t] += hk * sWb[k * ED + t];
        }
    }
    g_Ph[i] = pack8h(p);
    g_Qh[i] = pack8h(q);
}

// ---------------- per-layer edge kernel (2 edges / thread) -------------------
// new_e = relu(P[src] + Q[dst] + e @ Wc + be);  agg[dst] += new_e;  e += new_e
__global__ void __launch_bounds__(256) k_edge(const int* __restrict__ edge_index,
                       const float* __restrict__ We_l,   // full [L,72,8]
                       const float* __restrict__ be_l,   // full [L,8]
                       int layer) {
    __shared__ float sWc[ED * ED], sBe[ED];
    {
        const float* Wc = We_l + (size_t)layer * (2 * ND + ED) * ED + 2 * ND * ED;
        if (threadIdx.x < ED * ED) sWc[threadIdx.x] = Wc[threadIdx.x];
        if (threadIdx.x < ED) sBe[threadIdx.x] = be_l[layer * ED + threadIdx.x];
    }
    __syncthreads();
    int t2 = blockIdx.x * blockDim.x + threadIdx.x;
    int i0 = t2 * 2;
    if (i0 >= EE) return;
    // indices for both edges
    int s0 = edge_index[i0],      s1 = edge_index[i0 + 1];
    int d0 = edge_index[EE + i0], d1 = edge_index[EE + i0 + 1];
    // issue all random gathers early (fp16-packed rows: one LDG.128 each)
    uint4 pv0 = __ldg(&g_Ph[s0]);
    uint4 pv1 = __ldg(&g_Ph[s1]);
    uint4 qv0 = __ldg(&g_Qh[d0]);
    uint4 qv1 = __ldg(&g_Qh[d1]);
    // streamed e loads (4 consecutive float4 = 2 edges)
    float4* ep = (float4*)(g_e + (size_t)i0 * ED);
    float4 e0 = ep[0], e1 = ep[1], e2 = ep[2], e3 = ep[3];

    float m0[ED] = {e0.x, e0.y, e0.z, e0.w, e1.x, e1.y, e1.z, e1.w};
    float m1[ED] = {e2.x, e2.y, e2.z, e2.w, e3.x, e3.y, e3.z, e3.w};
    float t0[ED], t1[ED];
#pragma unroll
    for (int j = 0; j < ED; j++) { t0[j] = sBe[j]; t1[j] = sBe[j]; }
#pragma unroll
    for (int k = 0; k < ED; k++) {
        float a = m0[k], b = m1[k];
#pragma unroll
        for (int j = 0; j < ED; j++) {
            float w = sWc[k * ED + j];
            t0[j] += a * w;
            t1[j] += b * w;
        }
    }
    float p0[ED], p1[ED], q0[ED], q1[ED];
    unpack8h(pv0, p0); unpack8h(pv1, p1);
    unpack8h(qv0, q0); unpack8h(qv1, q1);
    float ne0[ED], ne1[ED];
#pragma unroll
    for (int j = 0; j < ED; j++) {
        float v0 = t0[j] + p0[j] + q0[j];
        float v1 = t1[j] + p1[j] + q1[j];
        ne0[j] = v0 > 0.f ? v0 : 0.f;
        ne1[j] = v1 > 0.f ? v1 : 0.f;
    }
    float* a0 = g_agg + (size_t)d0 * ED;
    float* a1 = g_agg + (size_t)d1 * ED;
    red_add_v4(a0,     ne0[0], ne0[1], ne0[2], ne0[3]);
    red_add_v4(a0 + 4, ne0[4], ne0[5], ne0[6], ne0[7]);
    red_add_v4(a1,     ne1[0], ne1[1], ne1[2], ne1[3]);
    red_add_v4(a1 + 4, ne1[4], ne1[5], ne1[6], ne1[7]);
    ep[0] = make_float4(m0[0] + ne0[0], m0[1] + ne0[1], m0[2] + ne0[2], m0[3] + ne0[3]);
    ep[1] = make_float4(m0[4] + ne0[4], m0[5] + ne0[5], m0[6] + ne0[6], m0[7] + ne0[7]);
    ep[2] = make_float4(m1[0] + ne1[0], m1[1] + ne1[1], m1[2] + ne1[2], m1[3] + ne1[3]);
    ep[3] = make_float4(m1[4] + ne1[4], m1[5] + ne1[5], m1[6] + ne1[6], m1[7] + ne1[7]);
}

// ---------------- per-layer node kernel --------------------------------------
// h += relu([h, agg] @ Wn + bn); re-zero agg; if not last, compute next P/Q.
__global__ void k_node(const float* __restrict__ Wn_l,  // full [L,40,32]
                       const float* __restrict__ bn_l,  // full [L,32]
                       const float* __restrict__ We_l,  // full [L,72,8]
                       int layer, int last) {
    __shared__ float sWn[(ND + ED) * ND], sBn[ND];
    __shared__ float sWa[ND * ED], sWb[ND * ED];
    {
        const float* Wn = Wn_l + (size_t)layer * (ND + ED) * ND;
        for (int tt = threadIdx.x; tt < (ND + ED) * ND; tt += blockDim.x) sWn[tt] = Wn[tt];
        for (int tt = threadIdx.x; tt < ND; tt += blockDim.x) sBn[tt] = bn_l[layer * ND + tt];
        if (!last) {
            const float* Wa = We_l + (size_t)(layer + 1) * (2 * ND + ED) * ED;
            for (int tt = threadIdx.x; tt < ND * ED; tt += blockDim.x) {
                sWa[tt] = Wa[tt];
                sWb[tt] = Wa[ND * ED + tt];
            }
        }
    }
    __syncthreads();
    int i = blockIdx.x * blockDim.x + threadIdx.x;
    if (i >= NN) return;
    float m[ND + ED];
    float4* hp = (float4*)(g_h + (size_t)i * ND);
#pragma unroll
    for (int j4 = 0; j4 < ND / 4; j4++) {
        float4 v = hp[j4];
        m[4*j4] = v.x; m[4*j4+1] = v.y; m[4*j4+2] = v.z; m[4*j4+3] = v.w;
    }
    float4* ag = (float4*)(g_agg + (size_t)i * ED);
    float4 a0 = ag[0], a1 = ag[1];
    m[ND+0]=a0.x; m[ND+1]=a0.y; m[ND+2]=a0.z; m[ND+3]=a0.w;
    m[ND+4]=a1.x; m[ND+5]=a1.y; m[ND+6]=a1.z; m[ND+7]=a1.w;
    // reset agg for next layer / next replay (zero-invariant)
    ag[0] = make_float4(0.f, 0.f, 0.f, 0.f);
    ag[1] = make_float4(0.f, 0.f, 0.f, 0.f);

    float acc[ND];
#pragma unroll
    for (int j = 0; j < ND; j++) acc[j] = sBn[j];
    for (int k = 0; k < ND + ED; k++) {
        float mk = m[k];
#pragma unroll
        for (int j = 0; j < ND; j++) acc[j] += mk * sWn[k * ND + j];
    }
    float hn[ND];
#pragma unroll
    for (int j = 0; j < ND; j++) {
        float r = acc[j] > 0.f ? acc[j] : 0.f;
        hn[j] = m[j] + r;
    }
#pragma unroll
    for (int j4 = 0; j4 < ND / 4; j4++)
        hp[j4] = make_float4(hn[4*j4], hn[4*j4+1], hn[4*j4+2], hn[4*j4+3]);

    if (!last) {
        float p[ED], q[ED];
#pragma unroll
        for (int t = 0; t < ED; t++) { p[t] = 0.f; q[t] = 0.f; }
#pragma unroll
        for (int k = 0; k < ND; k++) {
            float hk = hn[k];
#pragma unroll
            for (int t = 0; t < ED; t++) {
                p[t] += hk * sWa[k * ED + t];
                q[t] += hk * sWb[k * ED + t];
            }
        }
        g_Ph[i] = pack8h(p);
        g_Qh[i] = pack8h(q);
    }
}

// ---------------- final stage -------------------------------------------------
__global__ void k_zero_pg() {
    int i = blockIdx.x * blockDim.x + threadIdx.x;
    if (i < GG) { g_mx[i] = 0u; g_sum[i] = 0.f; }
}

__global__ void k_cand(const int* __restrict__ cand,
                       const int* __restrict__ batch,
                       const float* __restrict__ Wout,
                       const float* __restrict__ bout) {
    int c = blockIdx.x * blockDim.x + threadIdx.x;
    if (c >= NC) return;
    int node = cand[c];
    const float* hr = g_h + (size_t)node * ND;
    float v = bout[0];
#pragma unroll
    for (int j = 0; j < ND; j++) v += hr[j] * Wout[j];
    g_logits[c] = v;
    int gidx = batch[node];
    atomicMax(&g_mx[gidx], enc_f(v));
}

__global__ void k_shift(const int* __restrict__ cand,
                        const int* __restrict__ batch,
                        float* __restrict__ out) {
    int c = blockIdx.x * blockDim.x + threadIdx.x;
    if (c >= NC) return;
    int gidx = batch[cand[c]];
    float s = g_logits[c] - dec_f(g_mx[gidx]);
    out[c] = s;
    atomicAdd(&g_sum[gidx], expf(s));
}

__global__ void k_finish(const int* __restrict__ cand,
                         const int* __restrict__ batch,
                         float* __restrict__ out) {
    int c = blockIdx.x * blockDim.x + threadIdx.x;
    if (c >= NC) return;
    int gidx = batch[cand[c]];
    out[c] = out[c] - logf(g_sum[gidx]);
}

// ---------------- launch ------------------------------------------------------
extern "C" void kernel_launch(void* const* d_in, const int* in_sizes, int n_in,
                              void* d_out, int out_size) {
    const float* x        = (const float*)d_in[0];
    const float* edge_attr= (const float*)d_in[1];
    const float* Wn_in    = (const float*)d_in[2];
    const float* bn_in    = (const float*)d_in[3];
    const float* We_in    = (const float*)d_in[4];
    const float* be_in    = (const float*)d_in[5];
    const float* We_l     = (const float*)d_in[6];
    const float* be_l     = (const float*)d_in[7];
    const float* Wn_l     = (const float*)d_in[8];
    const float* bn_l     = (const float*)d_in[9];
    const float* Wout     = (const float*)d_in[10];
    const float* bout     = (const float*)d_in[11];
    const int*   edge_index = (const int*)d_in[12];
    const int*   batch    = (const int*)d_in[13];
    const int*   cand     = (const int*)d_in[14];
    float* out = (float*)d_out;

    const int TB = 256;
    const int gE  = (EE + TB - 1) / TB;
    const int gE2 = (EE / 2 + TB - 1) / TB;
    const int gN  = (NN + TB - 1) / TB;
    const int gC  = (NC + TB - 1) / TB;
    const int gG  = (GG + TB - 1) / TB;

    k_zero_pg<<<gG, TB>>>();
    k_init_edges<<<gE, TB>>>(edge_attr, We_in, be_in);
    k_init_nodes<<<gN, TB>>>(x, Wn_in, bn_in, We_l);
    for (int l = 0; l < NL; l++) {
        k_edge<<<gE2, TB>>>(edge_index, We_l, be_l, l);
        k_node<<<gN, TB>>>(Wn_l, bn_l, We_l, l, (l == NL - 1) ? 1 : 0);
    }
    k_cand<<<gC, TB>>>(cand, batch, Wout, bout);
    k_shift<<<gC, TB>>>(cand, batch, out);
    k_finish<<<gC, TB>>>(cand, batch, out);
}

// round 8
// speedup vs baseline: 1.2014x; 1.1395x over previous
#include <cuda_runtime.h>
#include <cuda_fp16.h>
#include <cstdint>
#include <cstring>

#define NN 100000
#define EE 1600000
#define NC 10000
#define GG 1000
#define ND 32
#define ED 8
#define NL 4

// ---------------- scratch (device globals; no allocation allowed) -----------
__device__ float g_h[NN * ND];      // node embeddings (12.8 MB, fp32)
__device__ uint4 g_eh[EE];          // edge embeddings packed fp16 x8 (25.6 MB)
__device__ uint4 g_Ph[NN];          // h @ We[l][0:32]  packed fp16 x8
__device__ uint4 g_Qh[NN];          // h @ We[l][32:64] packed fp16 x8
__device__ float g_agg[NN * ED];    // segment-sum accumulator (zero-invariant)
__device__ float g_logits[NC];
__device__ unsigned g_mx[GG];       // encoded float max
__device__ float g_sum[GG];

// ---------------- helpers ----------------------------------------------------
__device__ __forceinline__ unsigned enc_f(float f) {
    unsigned u = __float_as_uint(f);
    return (u & 0x80000000u) ? ~u : (u | 0x80000000u);
}
__device__ __forceinline__ float dec_f(unsigned u) {
    return (u & 0x80000000u) ? __uint_as_float(u & 0x7FFFFFFFu)
                             : __uint_as_float(~u);
}
__device__ __forceinline__ void red_add_v4(float* p, float a, float b, float c, float d) {
    asm volatile("red.global.add.v4.f32 [%0], {%1,%2,%3,%4};"
                 :: "l"(p), "f"(a), "f"(b), "f"(c), "f"(d) : "memory");
}
__device__ __forceinline__ unsigned h2u(__half2 h) {
    unsigned u; memcpy(&u, &h, 4); return u;
}
__device__ __forceinline__ float2 u2f2(unsigned u) {
    __half2 h; memcpy(&h, &u, 4); return __half22float2(h);
}
__device__ __forceinline__ uint4 pack8h(const float* v) {
    uint4 r;
    r.x = h2u(__floats2half2_rn(v[0], v[1]));
    r.y = h2u(__floats2half2_rn(v[2], v[3]));
    r.z = h2u(__floats2half2_rn(v[4], v[5]));
    r.w = h2u(__floats2half2_rn(v[6], v[7]));
    return r;
}
__device__ __forceinline__ void unpack8h(uint4 u, float* v) {
    float2 a = u2f2(u.x), b = u2f2(u.y), c = u2f2(u.z), d = u2f2(u.w);
    v[0]=a.x; v[1]=a.y; v[2]=b.x; v[3]=b.y; v[4]=c.x; v[5]=c.y; v[6]=d.x; v[7]=d.y;
}

// ---------------- init: e = edge_attr @ We_in + be_in (fp16 packed) ----------
__global__ void k_init_edges(const float* __restrict__ edge_attr,
                             const float* __restrict__ We_in,
                             const float* __restrict__ be_in) {
    __shared__ float sw[ED], sb[ED];
    if (threadIdx.x < ED) { sw[threadIdx.x] = We_in[threadIdx.x]; sb[threadIdx.x] = be_in[threadIdx.x]; }
    __syncthreads();
    int i = blockIdx.x * blockDim.x + threadIdx.x;
    if (i >= EE) return;
    float a = edge_attr[i];
    float v[ED];
#pragma unroll
    for (int j = 0; j < ED; j++) v[j] = a * sw[j] + sb[j];
    g_eh[i] = pack8h(v);
}

// ---------------- init: h = x @ Wn_in + bn_in; P0/Q0 from We_l[0] ------------
__global__ void k_init_nodes(const float* __restrict__ x,
                             const float* __restrict__ Wn_in,
                             const float* __restrict__ bn_in,
                             const float* __restrict__ We_l) {  // layer 0 block
    __shared__ float sW[2 * ND], sB[ND], sWa[ND * ED], sWb[ND * ED];
    for (int t = threadIdx.x; t < 2 * ND; t += blockDim.x) sW[t] = Wn_in[t];
    for (int t = threadIdx.x; t < ND; t += blockDim.x) sB[t] = bn_in[t];
    for (int t = threadIdx.x; t < ND * ED; t += blockDim.x) {
        sWa[t] = We_l[t];               // rows 0..31
        sWb[t] = We_l[ND * ED + t];     // rows 32..63
    }
    __syncthreads();
    int i = blockIdx.x * blockDim.x + threadIdx.x;
    if (i >= NN) return;
    float x0 = x[2 * i], x1 = x[2 * i + 1];
    float h[ND];
#pragma unroll
    for (int j = 0; j < ND; j++) h[j] = x0 * sW[j] + x1 * sW[ND + j] + sB[j];
    float4* ho = (float4*)(g_h + (size_t)i * ND);
#pragma unroll
    for (int j4 = 0; j4 < ND / 4; j4++)
        ho[j4] = make_float4(h[4*j4], h[4*j4+1], h[4*j4+2], h[4*j4+3]);
    float p[ED], q[ED];
#pragma unroll
    for (int t = 0; t < ED; t++) { p[t] = 0.f; q[t] = 0.f; }
#pragma unroll
    for (int k = 0; k < ND; k++) {
        float hk = h[k];
#pragma unroll
        for (int t = 0; t < ED; t++) {
            p[t] += hk * sWa[k * ED + t];
            q[t] += hk * sWb[k * ED + t];
        }
    }
    g_Ph[i] = pack8h(p);
    g_Qh[i] = pack8h(q);
}

// ---------------- per-layer edge kernel (2 edges / thread) -------------------
// new_e = relu(P[src] + Q[dst] + e @ Wc + be);  agg[dst] += new_e;  e += new_e
__global__ void __launch_bounds__(256, 5)
k_edge(const int* __restrict__ edge_index,
       const float* __restrict__ We_l,   // full [L,72,8]
       const float* __restrict__ be_l,   // full [L,8]
       int layer) {
    __shared__ float sWc[ED * ED], sBe[ED];
    {
        const float* Wc = We_l + (size_t)layer * (2 * ND + ED) * ED + 2 * ND * ED;
        if (threadIdx.x < ED * ED) sWc[threadIdx.x] = Wc[threadIdx.x];
        if (threadIdx.x < ED) sBe[threadIdx.x] = be_l[layer * ED + threadIdx.x];
    }
    __syncthreads();
    int t2 = blockIdx.x * blockDim.x + threadIdx.x;
    int i0 = t2 * 2;
    if (i0 >= EE) return;
    // vectorized index loads (i0 even -> 8B aligned)
    int2 sp = ((const int2*)edge_index)[t2];
    int2 dp = ((const int2*)(edge_index + EE))[t2];
    // issue all random gathers early (one LDG.128 each)
    uint4 pv0 = __ldg(&g_Ph[sp.x]);
    uint4 pv1 = __ldg(&g_Ph[sp.y]);
    uint4 qv0 = __ldg(&g_Qh[dp.x]);
    uint4 qv1 = __ldg(&g_Qh[dp.y]);
    // streamed fp16 e loads (one LDG.128 per edge)
    uint4 ea0 = g_eh[i0];
    uint4 ea1 = g_eh[i0 + 1];

    float m0[ED], m1[ED];
    unpack8h(ea0, m0);
    unpack8h(ea1, m1);
    float t0[ED], t1[ED];
#pragma unroll
    for (int j = 0; j < ED; j++) { t0[j] = sBe[j]; t1[j] = sBe[j]; }
#pragma unroll
    for (int k = 0; k < ED; k++) {
        float a = m0[k], b = m1[k];
#pragma unroll
        for (int j = 0; j < ED; j++) {
            float w = sWc[k * ED + j];
            t0[j] += a * w;
            t1[j] += b * w;
        }
    }
    // lazy unpack of P/Q: consume half2 pairs directly
    float ne0[ED], ne1[ED];
    {
        const unsigned* pu0 = &pv0.x; const unsigned* qu0 = &qv0.x;
        const unsigned* pu1 = &pv1.x; const unsigned* qu1 = &qv1.x;
#pragma unroll
        for (int jp = 0; jp < 4; jp++) {
            float2 pf0 = u2f2(pu0[jp]), qf0 = u2f2(qu0[jp]);
            float2 pf1 = u2f2(pu1[jp]), qf1 = u2f2(qu1[jp]);
            float v0a = t0[2*jp]   + pf0.x + qf0.x;
            float v0b = t0[2*jp+1] + pf0.y + qf0.y;
            float v1a = t1[2*jp]   + pf1.x + qf1.x;
            float v1b = t1[2*jp+1] + pf1.y + qf1.y;
            ne0[2*jp]   = v0a > 0.f ? v0a : 0.f;
            ne0[2*jp+1] = v0b > 0.f ? v0b : 0.f;
            ne1[2*jp]   = v1a > 0.f ? v1a : 0.f;
            ne1[2*jp+1] = v1b > 0.f ? v1b : 0.f;
        }
    }
    float* a0 = g_agg + (size_t)dp.x * ED;
    float* a1 = g_agg + (size_t)dp.y * ED;
    red_add_v4(a0,     ne0[0], ne0[1], ne0[2], ne0[3]);
    red_add_v4(a0 + 4, ne0[4], ne0[5], ne0[6], ne0[7]);
    red_add_v4(a1,     ne1[0], ne1[1], ne1[2], ne1[3]);
    red_add_v4(a1 + 4, ne1[4], ne1[5], ne1[6], ne1[7]);
    // residual e += new_e, repack fp16
    float r0[ED], r1[ED];
#pragma unroll
    for (int j = 0; j < ED; j++) { r0[j] = m0[j] + ne0[j]; r1[j] = m1[j] + ne1[j]; }
    g_eh[i0]     = pack8h(r0);
    g_eh[i0 + 1] = pack8h(r1);
}

// ---------------- per-layer node kernel --------------------------------------
// h += relu([h, agg] @ Wn + bn); re-zero agg; if not last, compute next P/Q.
__global__ void k_node(const float* __restrict__ Wn_l,  // full [L,40,32]
                       const float* __restrict__ bn_l,  // full [L,32]
                       const float* __restrict__ We_l,  // full [L,72,8]
                       int layer, int last) {
    __shared__ float sWn[(ND + ED) * ND], sBn[ND];
    __shared__ float sWa[ND * ED], sWb[ND * ED];
    {
        const float* Wn = Wn_l + (size_t)layer * (ND + ED) * ND;
        for (int tt = threadIdx.x; tt < (ND + ED) * ND; tt += blockDim.x) sWn[tt] = Wn[tt];
        for (int tt = threadIdx.x; tt < ND; tt += blockDim.x) sBn[tt] = bn_l[layer * ND + tt];
        if (!last) {
            const float* Wa = We_l + (size_t)(layer + 1) * (2 * ND + ED) * ED;
            for (int tt = threadIdx.x; tt < ND * ED; tt += blockDim.x) {
                sWa[tt] = Wa[tt];
                sWb[tt] = Wa[ND * ED + tt];
            }
        }
    }
    __syncthreads();
    int i = blockIdx.x * blockDim.x + threadIdx.x;
    if (i >= NN) return;
    float m[ND + ED];
    float4* hp = (float4*)(g_h + (size_t)i * ND);
#pragma unroll
    for (int j4 = 0; j4 < ND / 4; j4++) {
        float4 v = hp[j4];
        m[4*j4] = v.x; m[4*j4+1] = v.y; m[4*j4+2] = v.z; m[4*j4+3] = v.w;
    }
    float4* ag = (float4*)(g_agg + (size_t)i * ED);
    float4 a0 = ag[0], a1 = ag[1];
    m[ND+0]=a0.x; m[ND+1]=a0.y; m[ND+2]=a0.z; m[ND+3]=a0.w;
    m[ND+4]=a1.x; m[ND+5]=a1.y; m[ND+6]=a1.z; m[ND+7]=a1.w;
    // reset agg for next layer / next replay (zero-invariant)
    ag[0] = make_float4(0.f, 0.f, 0.f, 0.f);
    ag[1] = make_float4(0.f, 0.f, 0.f, 0.f);

    float acc[ND];
#pragma unroll
    for (int j = 0; j < ND; j++) acc[j] = sBn[j];
    for (int k = 0; k < ND + ED; k++) {
        float mk = m[k];
#pragma unroll
        for (int j = 0; j < ND; j++) acc[j] += mk * sWn[k * ND + j];
    }
    float hn[ND];
#pragma unroll
    for (int j = 0; j < ND; j++) {
        float r = acc[j] > 0.f ? acc[j] : 0.f;
        hn[j] = m[j] + r;
    }
#pragma unroll
    for (int j4 = 0; j4 < ND / 4; j4++)
        hp[j4] = make_float4(hn[4*j4], hn[4*j4+1], hn[4*j4+2], hn[4*j4+3]);

    if (!last) {
        float p[ED], q[ED];
#pragma unroll
        for (int t = 0; t < ED; t++) { p[t] = 0.f; q[t] = 0.f; }
#pragma unroll
        for (int k = 0; k < ND; k++) {
            float hk = hn[k];
#pragma unroll
            for (int t = 0; t < ED; t++) {
                p[t] += hk * sWa[k * ED + t];
                q[t] += hk * sWb[k * ED + t];
            }
        }
        g_Ph[i] = pack8h(p);
        g_Qh[i] = pack8h(q);
    }
}

// ---------------- final stage -------------------------------------------------
__global__ void k_zero_pg() {
    int i = blockIdx.x * blockDim.x + threadIdx.x;
    if (i < GG) { g_mx[i] = 0u; g_sum[i] = 0.f; }
}

__global__ void k_cand(const int* __restrict__ cand,
                       const int* __restrict__ batch,
                       const float* __restrict__ Wout,
                       const float* __restrict__ bout) {
    int c = blockIdx.x * blockDim.x + threadIdx.x;
    if (c >= NC) return;
    int node = cand[c];
    const float* hr = g_h + (size_t)node * ND;
    float v = bout[0];
#pragma unroll
    for (int j = 0; j < ND; j++) v += hr[j] * Wout[j];
    g_logits[c] = v;
    int gidx = batch[node];
    atomicMax(&g_mx[gidx], enc_f(v));
}

__global__ void k_shift(const int* __restrict__ cand,
                        const int* __restrict__ batch,
                        float* __restrict__ out) {
    int c = blockIdx.x * blockDim.x + threadIdx.x;
    if (c >= NC) return;
    int gidx = batch[cand[c]];
    float s = g_logits[c] - dec_f(g_mx[gidx]);
    out[c] = s;
    atomicAdd(&g_sum[gidx], expf(s));
}

__global__ void k_finish(const int* __restrict__ cand,
                         const int* __restrict__ batch,
                         float* __restrict__ out) {
    int c = blockIdx.x * blockDim.x + threadIdx.x;
    if (c >= NC) return;
    int gidx = batch[cand[c]];
    out[c] = out[c] - logf(g_sum[gidx]);
}

// ---------------- launch ------------------------------------------------------
extern "C" void kernel_launch(void* const* d_in, const int* in_sizes, int n_in,
                              void* d_out, int out_size) {
    const float* x        = (const float*)d_in[0];
    const float* edge_attr= (const float*)d_in[1];
    const float* Wn_in    = (const float*)d_in[2];
    const float* bn_in    = (const float*)d_in[3];
    const float* We_in    = (const float*)d_in[4];
    const float* be_in    = (const float*)d_in[5];
    const float* We_l     = (const float*)d_in[6];
    const float* be_l     = (const float*)d_in[7];
    const float* Wn_l     = (const float*)d_in[8];
    const float* bn_l     = (const float*)d_in[9];
    const float* Wout     = (const float*)d_in[10];
    const float* bout     = (const float*)d_in[11];
    const int*   edge_index = (const int*)d_in[12];
    const int*   batch    = (const int*)d_in[13];
    const int*   cand     = (const int*)d_in[14];
    float* out = (float*)d_out;

    const int TB = 256;
    const int gE  = (EE + TB - 1) / TB;
    const int gE2 = (EE / 2 + TB - 1) / TB;
    const int gN  = (NN + TB - 1) / TB;
    const int gC  = (NC + TB - 1) / TB;
    const int gG  = (GG + TB - 1) / TB;

    k_zero_pg<<<gG, TB>>>();
    k_init_edges<<<gE, TB>>>(edge_attr, We_in, be_in);
    k_init_nodes<<<gN, TB>>>(x, Wn_in, bn_in, We_l);
    for (int l = 0; l < NL; l++) {
        k_edge<<<gE2, TB>>>(edge_index, We_l, be_l, l);
        k_node<<<gN, TB>>>(Wn_l, bn_l, We_l, l, (l == NL - 1) ? 1 : 0);
    }
    k_cand<<<gC, TB>>>(cand, batch, Wout, bout);
    k_shift<<<gC, TB>>>(cand, batch, out);
    k_finish<<<gC, TB>>>(cand, batch, out);
}